// round 5
// baseline (speedup 1.0000x reference)
#include <cuda_runtime.h>
#include <cstdint>

// WeightedMseLoss: out = mean( (x - y)^2 * weight_table[round(y*100)] )
// Inputs: d_in[0]=x (f32, N), d_in[1]=y (f32, N), d_in[2]=weight_table (f32, 101)
// Output: 1 x f32 scalar.
//
// R5: latency-bound fix. cp.async.cg (16B, L1-bypass) stages x/y tiles into
// smem per-thread (no cross-thread sharing, no in-loop barriers). 3-stage
// pipeline -> ~192KB in flight per SM without register pressure.
// Tail iterations use src-size=0 zero-fill (contributes exactly 0).
// Single wave (1184 blocks), fused deterministic last-block finalize.

#define NBLOCKS    1184     // 148 SMs * 8 blocks -> one wave
#define NTHREADS   256
#define NUM_LEVELS 101
#define STAGES     3

__device__ float        g_partials[NBLOCKS];
__device__ unsigned int g_ticket = 0;

__device__ __forceinline__ void cp_async16(uint32_t dst_smem, const void* src, int src_bytes)
{
    // src_bytes == 16: normal copy; == 0: zero-fill destination, no gmem access
    asm volatile("cp.async.cg.shared.global [%0], [%1], 16, %2;\n"
                 :: "r"(dst_smem), "l"(src), "r"(src_bytes));
}
__device__ __forceinline__ void cp_commit()
{
    asm volatile("cp.async.commit_group;\n" ::: "memory");
}
__device__ __forceinline__ void cp_wait_allow2()
{
    asm volatile("cp.async.wait_group 2;\n" ::: "memory");  // STAGES-1
}

__global__ __launch_bounds__(NTHREADS) void wmse_kernel(
    const float4* __restrict__ x4,
    const float4* __restrict__ y4,
    const float* __restrict__ wt,
    int n4,       // number of float4 vectors
    int niter,    // ceil(n4 / (gridDim*blockDim)), uniform for all threads
    float invN,
    float* __restrict__ out)
{
    __shared__ float  s_w[NUM_LEVELS];
    __shared__ float4 s_x[STAGES][NTHREADS];
    __shared__ float4 s_y[STAGES][NTHREADS];

    const int t = threadIdx.x;
    if (t < NUM_LEVELS) s_w[t] = wt[t];
    __syncthreads();

    const int stride = gridDim.x * blockDim.x;
    const int base   = blockIdx.x * blockDim.x + t;

    const uint32_t sx0 = (uint32_t)__cvta_generic_to_shared(&s_x[0][t]);
    const uint32_t sy0 = (uint32_t)__cvta_generic_to_shared(&s_y[0][t]);
    const uint32_t stage_bytes = NTHREADS * 16;

    // ---- prologue: issue stages 0..STAGES-1 ----
    #pragma unroll
    for (int s = 0; s < STAGES; s++) {
        int i = base + s * stride;
        bool ok = (i < n4);
        int  sz = ok ? 16 : 0;
        const float4* xs = ok ? (x4 + i) : x4;   // clamped addr; not accessed when sz=0
        const float4* ys = ok ? (y4 + i) : y4;
        cp_async16(sx0 + s * stage_bytes, xs, sz);
        cp_async16(sy0 + s * stage_bytes, ys, sz);
        cp_commit();
    }

    float acc = 0.0f;
    int   i   = base;
    int   buf = 0;

    for (int j = 0; j < niter; j++, i += stride) {
        cp_wait_allow2();   // group j complete (every iter commits exactly one group)

        float4 xv = s_x[buf][t];
        float4 yv = s_y[buf][t];

        // refill this buffer for iteration j+STAGES (empty group if out of range)
        {
            int inext = i + STAGES * stride;
            bool ok = (inext < n4);
            int  sz = ok ? 16 : 0;
            const float4* xs = ok ? (x4 + inext) : x4;
            const float4* ys = ok ? (y4 + inext) : y4;
            cp_async16(sx0 + buf * stage_bytes, xs, sz);
            cp_async16(sy0 + buf * stage_bytes, ys, sz);
            cp_commit();
        }
        buf = (buf == STAGES - 1) ? 0 : buf + 1;

        // compute (zero-filled tail: y=0 -> idx 0, diff 0 -> term 0)
        int i0 = __float2int_rn(yv.x * 100.0f);
        int i1 = __float2int_rn(yv.y * 100.0f);
        int i2 = __float2int_rn(yv.z * 100.0f);
        int i3 = __float2int_rn(yv.w * 100.0f);
        float d0 = xv.x - yv.x, d1 = xv.y - yv.y;
        float d2 = xv.z - yv.z, d3 = xv.w - yv.w;
        acc = fmaf(d0 * d0, s_w[i0], acc);
        acc = fmaf(d1 * d1, s_w[i1], acc);
        acc = fmaf(d2 * d2, s_w[i2], acc);
        acc = fmaf(d3 * d3, s_w[i3], acc);
    }

    // ---- block reduce ----
    #pragma unroll
    for (int o = 16; o > 0; o >>= 1)
        acc += __shfl_down_sync(0xffffffffu, acc, o);

    __shared__ float s_sum[NTHREADS / 32];
    __shared__ bool  s_last;
    if ((t & 31) == 0) s_sum[t >> 5] = acc;
    __syncthreads();

    if (t < 32) {
        float v = (t < NTHREADS / 32) ? s_sum[t] : 0.0f;
        #pragma unroll
        for (int o = 4; o > 0; o >>= 1)
            v += __shfl_down_sync(0xffffffffu, v, o);
        if (t == 0) {
            g_partials[blockIdx.x] = v;
            __threadfence();
            unsigned int ticket = atomicAdd(&g_ticket, 1u);
            s_last = (ticket == (unsigned int)(gridDim.x - 1));
        }
    }
    __syncthreads();

    // ---- last block: deterministic final reduce ----
    if (s_last) {
        float a = 0.0f;
        for (int k = t; k < NBLOCKS; k += NTHREADS)
            a += g_partials[k];          // fixed order per thread -> deterministic

        #pragma unroll
        for (int o = 16; o > 0; o >>= 1)
            a += __shfl_down_sync(0xffffffffu, a, o);

        __shared__ float s_fin[NTHREADS / 32];
        if ((t & 31) == 0) s_fin[t >> 5] = a;
        __syncthreads();

        if (t < 32) {
            float v = (t < NTHREADS / 32) ? s_fin[t] : 0.0f;
            #pragma unroll
            for (int o = 4; o > 0; o >>= 1)
                v += __shfl_down_sync(0xffffffffu, v, o);
            if (t == 0) {
                out[0] = v * invN;
                g_ticket = 0;   // reset for next graph replay
            }
        }
    }
}

extern "C" void kernel_launch(void* const* d_in, const int* in_sizes, int n_in,
                              void* d_out, int out_size)
{
    const float* x  = (const float*)d_in[0];
    const float* y  = (const float*)d_in[1];
    const float* wt = (const float*)d_in[2];
    float* out = (float*)d_out;

    const int n      = in_sizes[0];
    const int n4     = n >> 2;                       // N divisible by 4
    const int stride = NBLOCKS * NTHREADS;
    const int niter  = (n4 + stride - 1) / stride;   // uniform; tail zero-filled

    wmse_kernel<<<NBLOCKS, NTHREADS>>>(
        (const float4*)x, (const float4*)y, wt, n4, niter, 1.0f / (float)n, out);
}

// round 6
// speedup vs baseline: 1.1044x; 1.1044x over previous
#include <cuda_runtime.h>

// WeightedMseLoss: out = mean( (x - y)^2 * weight_table[round(y*100)] )
// Inputs: d_in[0]=x (f32, N), d_in[1]=y (f32, N), d_in[2]=weight_table (f32, 101)
// Output: 1 x f32 scalar.
//
// R6: R1/R4's proven streaming loop (simple smem LUT, 2-deep unroll,
// 4 LDG.128 in flight, 32 regs, single wave) with a near-zero-cost ending:
// one atomicAdd(out) per block. out is zeroed each launch by a 4-byte
// cudaMemsetAsync (graph-capturable, allocation-free). No ticket, no
// threadfence, no second kernel.

#define NBLOCKS    1184     // 148 SMs * 8 blocks -> one wave
#define NTHREADS   256
#define NUM_LEVELS 101

__global__ __launch_bounds__(NTHREADS) void wmse_kernel(
    const float* __restrict__ x,
    const float* __restrict__ y,
    const float* __restrict__ wt,
    int n4,        // number of float4 vectors
    float invN,
    float* __restrict__ out)
{
    __shared__ float s_w[NUM_LEVELS];
    const int t = threadIdx.x;
    if (t < NUM_LEVELS) s_w[t] = wt[t];
    __syncthreads();

    const float4* __restrict__ x4 = reinterpret_cast<const float4*>(x);
    const float4* __restrict__ y4 = reinterpret_cast<const float4*>(y);

    float acc = 0.0f;
    const int stride = gridDim.x * blockDim.x;
    int i = blockIdx.x * blockDim.x + t;

    // 2-deep unroll: 4 independent 16B LDGs in flight per iteration
    for (; i + stride < n4; i += 2 * stride) {
        float4 xa = x4[i];
        float4 ya = y4[i];
        float4 xb = x4[i + stride];
        float4 yb = y4[i + stride];

        int ia0 = __float2int_rn(ya.x * 100.0f);
        int ia1 = __float2int_rn(ya.y * 100.0f);
        int ia2 = __float2int_rn(ya.z * 100.0f);
        int ia3 = __float2int_rn(ya.w * 100.0f);
        float da0 = xa.x - ya.x, da1 = xa.y - ya.y;
        float da2 = xa.z - ya.z, da3 = xa.w - ya.w;
        acc = fmaf(da0 * da0, s_w[ia0], acc);
        acc = fmaf(da1 * da1, s_w[ia1], acc);
        acc = fmaf(da2 * da2, s_w[ia2], acc);
        acc = fmaf(da3 * da3, s_w[ia3], acc);

        int ib0 = __float2int_rn(yb.x * 100.0f);
        int ib1 = __float2int_rn(yb.y * 100.0f);
        int ib2 = __float2int_rn(yb.z * 100.0f);
        int ib3 = __float2int_rn(yb.w * 100.0f);
        float db0 = xb.x - yb.x, db1 = xb.y - yb.y;
        float db2 = xb.z - yb.z, db3 = xb.w - yb.w;
        acc = fmaf(db0 * db0, s_w[ib0], acc);
        acc = fmaf(db1 * db1, s_w[ib1], acc);
        acc = fmaf(db2 * db2, s_w[ib2], acc);
        acc = fmaf(db3 * db3, s_w[ib3], acc);
    }
    for (; i < n4; i += stride) {
        float4 xv = x4[i];
        float4 yv = y4[i];
        int i0 = __float2int_rn(yv.x * 100.0f);
        int i1 = __float2int_rn(yv.y * 100.0f);
        int i2 = __float2int_rn(yv.z * 100.0f);
        int i3 = __float2int_rn(yv.w * 100.0f);
        float d0 = xv.x - yv.x, d1 = xv.y - yv.y;
        float d2 = xv.z - yv.z, d3 = xv.w - yv.w;
        acc = fmaf(d0 * d0, s_w[i0], acc);
        acc = fmaf(d1 * d1, s_w[i1], acc);
        acc = fmaf(d2 * d2, s_w[i2], acc);
        acc = fmaf(d3 * d3, s_w[i3], acc);
    }

    // block reduce
    #pragma unroll
    for (int o = 16; o > 0; o >>= 1)
        acc += __shfl_down_sync(0xffffffffu, acc, o);

    __shared__ float s_sum[NTHREADS / 32];
    if ((t & 31) == 0) s_sum[t >> 5] = acc;
    __syncthreads();

    if (t < 32) {
        float v = (t < NTHREADS / 32) ? s_sum[t] : 0.0f;
        #pragma unroll
        for (int o = 4; o > 0; o >>= 1)
            v += __shfl_down_sync(0xffffffffu, v, o);
        if (t == 0)
            atomicAdd(out, v * invN);   // one atomic per block
    }
}

extern "C" void kernel_launch(void* const* d_in, const int* in_sizes, int n_in,
                              void* d_out, int out_size)
{
    const float* x  = (const float*)d_in[0];
    const float* y  = (const float*)d_in[1];
    const float* wt = (const float*)d_in[2];
    float* out = (float*)d_out;

    const int n  = in_sizes[0];
    const int n4 = n >> 2;  // N = 2^24, divisible by 4

    // zero the accumulator each launch (graph-capturable, allocation-free)
    cudaMemsetAsync(out, 0, sizeof(float));

    wmse_kernel<<<NBLOCKS, NTHREADS>>>(x, y, wt, n4, 1.0f / (float)n, out);
}